// round 11
// baseline (speedup 1.0000x reference)
#include <cuda_runtime.h>
#include <stdint.h>

constexpr int B  = 2;
constexpr int S  = 2048;
constexpr int D  = 1024;
constexpr int H  = 16;
constexpr int HD = 64;
constexpr int M  = B * S;   // 4096

// Scratch (device globals — no allocation allowed)
__device__ float g_q[(size_t)B * H * S * HD];
__device__ float g_k[(size_t)B * H * S * HD];
__device__ float g_vt[(size_t)B * H * HD * S];   // V transposed: [B,H,HD,S]
__device__ float g_attn[(size_t)B * S * D];
__device__ float g_xt[(size_t)M * D];            // tf32-rounded x
__device__ float g_wt[4 * (size_t)D * D];        // tf32-rounded Wq,Wk,Wv,Wp

__device__ __forceinline__ uint32_t f2tf(float f) {
    uint32_t u;
    asm("cvt.rna.tf32.f32 %0, %1;" : "=r"(u) : "f"(f));
    return u;
}
__device__ __forceinline__ float rndtf(float f) { return __uint_as_float(f2tf(f)); }

__device__ __forceinline__ void mma8(float* c,
                                     uint32_t a0, uint32_t a1, uint32_t a2, uint32_t a3,
                                     uint32_t b0, uint32_t b1) {
    asm volatile(
        "mma.sync.aligned.m16n8k8.row.col.f32.tf32.tf32.f32 "
        "{%0,%1,%2,%3},{%4,%5,%6,%7},{%8,%9},{%0,%1,%2,%3};"
        : "+f"(c[0]), "+f"(c[1]), "+f"(c[2]), "+f"(c[3])
        : "r"(a0), "r"(a1), "r"(a2), "r"(a3), "r"(b0), "r"(b1));
}

__device__ __forceinline__ uint4 ldsm4(uint32_t addr) {
    uint4 r;
    asm volatile("ldmatrix.sync.aligned.m8n8.x4.shared.b16 {%0,%1,%2,%3}, [%4];"
                 : "=r"(r.x), "=r"(r.y), "=r"(r.z), "=r"(r.w) : "r"(addr));
    return r;
}

__device__ __forceinline__ void cpa16(uint32_t dst, const void* src) {
    asm volatile("cp.async.cg.shared.global [%0], [%1], 16;" :: "r"(dst), "l"(src));
}
__device__ __forceinline__ void cpcommit() { asm volatile("cp.async.commit_group;"); }
template <int N>
__device__ __forceinline__ void cpwait() { asm volatile("cp.async.wait_group %0;" :: "n"(N)); }

// ---------------------------------------------------------------------------
// tf32 pre-round pass: x and the 4 weight matrices
// ---------------------------------------------------------------------------
__global__ __launch_bounds__(256)
void tf32_cvt(const float* __restrict__ x,  const float* __restrict__ wq,
              const float* __restrict__ wk, const float* __restrict__ wv,
              const float* __restrict__ wp,
              float* __restrict__ xo, float* __restrict__ qo,
              float* __restrict__ ko, float* __restrict__ vo, float* __restrict__ po)
{
    const float* s; float* d; int n;
    switch (blockIdx.y) {
        case 0: s = x;  d = xo; n = M * D; break;
        case 1: s = wq; d = qo; n = D * D; break;
        case 2: s = wk; d = ko; n = D * D; break;
        case 3: s = wv; d = vo; n = D * D; break;
        default: s = wp; d = po; n = D * D; break;
    }
    for (int i = (blockIdx.x * 256 + threadIdx.x) * 4; i < n; i += 512 * 256 * 4) {
        const float4 v = *(const float4*)(s + i);
        *(uint4*)(d + i) = make_uint4(f2tf(v.x), f2tf(v.y), f2tf(v.z), f2tf(v.w));
    }
}

// ---------------------------------------------------------------------------
// TF32 GEMM: C = A[M,1024] * W[1024,1024]^T + bias.  Inputs pre-rounded.
// Block 128x128, BK=16, 8 warps, warp tile 64x32. cp.async 4-stage pipeline.
// MODE 0: row-major fp32 out. MODE 2: QKV fused (z): z=0/1 scatter tf32 to
//   [B,H,S,HD] (Q scaled 0.125); z=2 scatter tf32 TRANSPOSED to [B,H,HD,S].
// ---------------------------------------------------------------------------
template <int MODE>
__global__ __launch_bounds__(256, 2)
void gemm_tc(const float* __restrict__ A,
             const float* __restrict__ W0, const float* __restrict__ b0_,
             const float* __restrict__ W1, const float* __restrict__ b1_,
             const float* __restrict__ W2, const float* __restrict__ b2_,
             float* __restrict__ C0, float* __restrict__ C1, float* __restrict__ C2)
{
    constexpr int K = 1024;
    constexpr int N = 1024;
    constexpr int NKB = 64;

    const float* W; const float* bias; float* C; int z = 0;
    if (MODE != 2) { W = W0; bias = b0_; C = C0; }
    else {
        z    = blockIdx.z;
        W    = (z == 0) ? W0 : (z == 1) ? W1 : W2;
        bias = (z == 0) ? b0_ : (z == 1) ? b1_ : b2_;
        C    = (z == 0) ? C0 : (z == 1) ? C1 : C2;
    }

    extern __shared__ __align__(16) uint32_t smg[];
    const uint32_t sbase = (uint32_t)__cvta_generic_to_shared(smg);

    const int t    = threadIdx.x;
    const int lane = t & 31;
    const int warp = t >> 5;
    const int gid  = lane >> 2;
    const int tig  = lane & 3;
    const int wm   = warp >> 2;
    const int wn   = warp & 3;
    const int bm   = blockIdx.y * 128;
    const int bn   = blockIdx.x * 128;

    // cp.async staging
    const int srow = t >> 2;
    const int sg   = t & 3;
    const float* sa0 = A + (size_t)(bm + srow) * K + sg * 4;
    const float* sw0 = W + (size_t)(bn + srow) * K + sg * 4;
    const uint32_t dsw = (uint32_t)(srow * 64 + ((sg ^ ((srow >> 1) & 3)) << 4));

    // ldmatrix fragment addresses (byte offsets within a stage)
    uint32_t relA[4], relB[2];
    {
        const int hiA = (lane >> 4) & 1;
#pragma unroll
        for (int mt = 0; mt < 4; mt++) {
            const int row = wm * 64 + mt * 16 + (lane & 7) + (lane & 8);
            relA[mt] = row * 64 + (uint32_t)((hiA ^ ((row >> 1) & 3)) << 4);
        }
        const int hiB = (lane >> 3) & 1;
#pragma unroll
        for (int n2 = 0; n2 < 2; n2++) {
            const int row = wn * 32 + n2 * 16 + (lane & 7) + ((lane >> 1) & 8);
            relB[n2] = 8192u + row * 64 + (uint32_t)((hiB ^ ((row >> 1) & 3)) << 4);
        }
    }

#define GISSUE(kb, st)                                            \
    {                                                             \
        const uint32_t dd = sbase + (uint32_t)(st) * 16384u + dsw;\
        const float* a = sa0 + (kb) * 16;                         \
        const float* w = sw0 + (kb) * 16;                         \
        cpa16(dd,          a);                                    \
        cpa16(dd + 4096,   a + (size_t)64 * K);                   \
        cpa16(dd + 8192,   w);                                    \
        cpa16(dd + 12288,  w + (size_t)64 * K);                   \
    }

    float acc[4][4][4];
#pragma unroll
    for (int i = 0; i < 4; i++)
#pragma unroll
        for (int j = 0; j < 4; j++)
#pragma unroll
            for (int l = 0; l < 4; l++) acc[i][j][l] = 0.f;

    GISSUE(0, 0); cpcommit();
    GISSUE(1, 1); cpcommit();
    GISSUE(2, 2); cpcommit();

    for (int kb = 0; kb < NKB; kb++) {
        cpwait<2>();
        __syncthreads();
        if (kb + 3 < NKB) GISSUE(kb + 3, (kb + 3) & 3);
        cpcommit();

        const uint32_t sbk = sbase + (uint32_t)((kb & 3) << 14);
#pragma unroll
        for (int ks = 0; ks < 2; ks++) {
            const uint32_t kx = (uint32_t)(ks << 5);
            uint4 af[4];
#pragma unroll
            for (int mt = 0; mt < 4; mt++)
                af[mt] = ldsm4(sbk + (relA[mt] ^ kx));
            const uint4 bq0 = ldsm4(sbk + (relB[0] ^ kx));
            const uint4 bq1 = ldsm4(sbk + (relB[1] ^ kx));
#pragma unroll
            for (int mt = 0; mt < 4; mt++) {
                mma8(acc[mt][0], af[mt].x, af[mt].y, af[mt].z, af[mt].w, bq0.x, bq0.y);
                mma8(acc[mt][1], af[mt].x, af[mt].y, af[mt].z, af[mt].w, bq0.z, bq0.w);
                mma8(acc[mt][2], af[mt].x, af[mt].y, af[mt].z, af[mt].w, bq1.x, bq1.y);
                mma8(acc[mt][3], af[mt].x, af[mt].y, af[mt].z, af[mt].w, bq1.z, bq1.w);
            }
        }
    }
#undef GISSUE

    // ---- epilogue ----
    const float qs = (MODE == 2 && z == 0) ? 0.125f : 1.0f;
#pragma unroll
    for (int mt = 0; mt < 4; mt++) {
        const int r1 = bm + wm * 64 + mt * 16 + gid;
        const int r2 = r1 + 8;
#pragma unroll
        for (int nt = 0; nt < 4; nt++) {
            const int n = bn + wn * 32 + nt * 8 + 2 * tig;
            const float bx = __ldg(&bias[n]), by = __ldg(&bias[n + 1]);
            if (MODE == 0) {
                *(float2*)&C[(size_t)r1 * N + n] =
                    make_float2(acc[mt][nt][0] + bx, acc[mt][nt][1] + by);
                *(float2*)&C[(size_t)r2 * N + n] =
                    make_float2(acc[mt][nt][2] + bx, acc[mt][nt][3] + by);
            } else {
                float2 v1 = make_float2(rndtf((acc[mt][nt][0] + bx) * qs),
                                        rndtf((acc[mt][nt][1] + by) * qs));
                float2 v2 = make_float2(rndtf((acc[mt][nt][2] + bx) * qs),
                                        rndtf((acc[mt][nt][3] + by) * qs));
                const int hh = n >> 6, ee = n & 63;
                const int b1r = r1 >> 11, s1r = r1 & (S - 1);
                const int b2r = r2 >> 11, s2r = r2 & (S - 1);
                if (z == 2) {
                    // transposed V store: [B,H,HD,S]
                    float* p1 = C + (((size_t)b1r * H + hh) * HD + ee) * S;
                    float* p2 = C + (((size_t)b2r * H + hh) * HD + ee) * S;
                    p1[s1r]     = v1.x;  p1[S + s1r] = v1.y;
                    p2[s2r]     = v2.x;  p2[S + s2r] = v2.y;
                } else {
                    *(float2*)&C[(((size_t)b1r * H + hh) * S + s1r) * HD + ee] = v1;
                    *(float2*)&C[(((size_t)b2r * H + hh) * S + s2r) * HD + ee] = v2;
                }
            }
        }
    }
}

// ---------------------------------------------------------------------------
// TF32 flash attention, 128-row Q tiles, 256 threads (8 warps; warp owns 16
// rows). cp.async double-buffered K (natural) and VT (pre-transposed [e][s]).
// All MMA operands via ldmatrix: Q/P A-frags, K/VT B-frags.
// Smem bytes: K0 @0, K1 @16384, VT0 @32768, VT1 @50176, QP @67584.
// Total 102400 B, 2 CTAs/SM.
// ---------------------------------------------------------------------------
constexpr uint32_t VT_B = 32768u;
constexpr uint32_t QP_B = 67584u;
constexpr int      QP_W = 16896;      // word offset of QP region

__global__ __launch_bounds__(256, 2)
void attn_tc(const float* __restrict__ q,
             const float* __restrict__ k,
             const float* __restrict__ vt,
             float* __restrict__ out)
{
    extern __shared__ __align__(16) uint32_t sma[];
    const uint32_t sb = (uint32_t)__cvta_generic_to_shared(sma);

    const int t    = threadIdx.x;
    const int lane = t & 31;
    const int warp = t >> 5;          // 0..7
    const int gid  = lane >> 2;
    const int tig  = lane & 3;
    const int rm   = warp * 16;

    const int hb = blockIdx.y, bb = blockIdx.z;
    const int m0 = blockIdx.x * 128;
    const size_t base = ((size_t)bb * H + hb) * S * HD;
    const float* qb  = q + base + (size_t)m0 * HD;
    const float* kb_ = k + base;
    const float* vtb = vt + ((size_t)bb * H + hb) * HD * S;

    const int crow = t >> 4;   // 0..15
    const int cg   = t & 15;

    // ---- issue Q (128 rows, group 0) ----
#pragma unroll
    for (int i = 0; i < 8; i++) {
        const int row = crow + i * 16;
        cpa16(sb + QP_B + row * 256 + (uint32_t)((cg ^ (row & 7)) << 4),
              qb + row * 64 + cg * 4);
    }
    cpcommit();

#define KV_ISSUE(n0, buf)                                                        \
    {                                                                            \
        const float* kp = kb_ + (size_t)(n0) * HD;                               \
        _Pragma("unroll")                                                        \
        for (int i = 0; i < 4; i++) {                                            \
            const int row = crow + i * 16;                                       \
            cpa16(sb + (uint32_t)(buf) * 16384u + row * 256 +                    \
                      (uint32_t)((cg ^ (row & 7)) << 4),                         \
                  kp + row * 64 + cg * 4);                                       \
        }                                                                        \
        _Pragma("unroll")                                                        \
        for (int i = 0; i < 4; i++) {                                            \
            const int row = crow + i * 16;   /* e row */                         \
            cpa16(sb + VT_B + (uint32_t)(buf) * 17408u + row * 272 +             \
                      (uint32_t)(cg << 4),                                       \
                  vtb + (size_t)row * S + (n0) + cg * 4);                        \
        }                                                                        \
    }

    KV_ISSUE(0, 0);  cpcommit();
    KV_ISSUE(64, 1); cpcommit();

    // ---- fragment addresses ----
    uint32_t relK[4], relV[4], relQ, relP;
    {
        const int hiB = (lane >> 3) & 1;
#pragma unroll
        for (int n2 = 0; n2 < 4; n2++) {
            const int row = n2 * 16 + (lane & 7) + ((lane >> 1) & 8);
            relK[n2] = row * 256 + (uint32_t)((hiB ^ (row & 7)) << 4);
            relV[n2] = VT_B + row * 272 + (uint32_t)(hiB << 4);
        }
        const int hiA  = (lane >> 4) & 1;
        const int rowq = rm + (lane & 7) + (lane & 8);
        relQ = QP_B + rowq * 256 + (uint32_t)((hiA ^ (rowq & 7)) << 4);
        relP = QP_B + rowq * 272 + (uint32_t)(hiA << 4);
    }

    cpwait<2>();
    __syncthreads();
    uint4 qf[8];
#pragma unroll
    for (int ks = 0; ks < 8; ks++)
        qf[ks] = ldsm4(sb + (relQ ^ (uint32_t)(ks << 5)));
    __syncthreads();   // Q fully in registers before QP region is reused for P

    float m1 = -1e30f, m2 = -1e30f, l1 = 0.f, l2 = 0.f;
    float o[8][4];
#pragma unroll
    for (int nt = 0; nt < 8; nt++)
#pragma unroll
        for (int j = 0; j < 4; j++) o[nt][j] = 0.f;

    for (int kt = 0; kt < 32; kt++) {
        cpwait<1>();
        __syncthreads();
        const uint32_t kbase = sb + (uint32_t)((kt & 1) << 14);
        const uint32_t vtoff = (uint32_t)((kt & 1) * 17408);

        // ---- scores = Q . K^T ----
        float sc[8][4];
#pragma unroll
        for (int nt = 0; nt < 8; nt++)
#pragma unroll
            for (int j = 0; j < 4; j++) sc[nt][j] = 0.f;
#pragma unroll
        for (int ks = 0; ks < 8; ks++) {
            const uint32_t kx = (uint32_t)(ks << 5);
#pragma unroll
            for (int n2 = 0; n2 < 4; n2++) {
                const uint4 bf = ldsm4(kbase + (relK[n2] ^ kx));
                mma8(sc[2 * n2],     qf[ks].x, qf[ks].y, qf[ks].z, qf[ks].w, bf.x, bf.y);
                mma8(sc[2 * n2 + 1], qf[ks].x, qf[ks].y, qf[ks].z, qf[ks].w, bf.z, bf.w);
            }
        }

        // ---- online softmax in registers ----
        float mx1 = -1e30f, mx2 = -1e30f;
#pragma unroll
        for (int nt = 0; nt < 8; nt++) {
            mx1 = fmaxf(mx1, fmaxf(sc[nt][0], sc[nt][1]));
            mx2 = fmaxf(mx2, fmaxf(sc[nt][2], sc[nt][3]));
        }
        mx1 = fmaxf(mx1, __shfl_xor_sync(0xffffffffu, mx1, 1));
        mx1 = fmaxf(mx1, __shfl_xor_sync(0xffffffffu, mx1, 2));
        mx2 = fmaxf(mx2, __shfl_xor_sync(0xffffffffu, mx2, 1));
        mx2 = fmaxf(mx2, __shfl_xor_sync(0xffffffffu, mx2, 2));
        const float M1 = fmaxf(m1, mx1);
        const float M2 = fmaxf(m2, mx2);

        float s1 = 0.f, s2 = 0.f;
#pragma unroll
        for (int nt = 0; nt < 8; nt++) {
            sc[nt][0] = __expf(sc[nt][0] - M1); s1 += sc[nt][0];
            sc[nt][1] = __expf(sc[nt][1] - M1); s1 += sc[nt][1];
            sc[nt][2] = __expf(sc[nt][2] - M2); s2 += sc[nt][2];
            sc[nt][3] = __expf(sc[nt][3] - M2); s2 += sc[nt][3];
        }
        s1 += __shfl_xor_sync(0xffffffffu, s1, 1);
        s1 += __shfl_xor_sync(0xffffffffu, s1, 2);
        s2 += __shfl_xor_sync(0xffffffffu, s2, 1);
        s2 += __shfl_xor_sync(0xffffffffu, s2, 2);

        const float c1 = __expf(m1 - M1);
        const float c2 = __expf(m2 - M2);
        l1 = l1 * c1 + s1;
        l2 = l2 * c2 + s2;
        m1 = M1; m2 = M2;
#pragma unroll
        for (int nt = 0; nt < 8; nt++) {
            o[nt][0] *= c1; o[nt][1] *= c1;
            o[nt][2] *= c2; o[nt][3] *= c2;
        }

        // ---- P -> smem (tf32), warp-private rows (stride 68 words) ----
#pragma unroll
        for (int nt = 0; nt < 8; nt++) {
            const int cc = nt * 8 + 2 * tig;
            *(uint2*)&sma[QP_W + (rm + gid) * 68 + cc] =
                make_uint2(f2tf(sc[nt][0]), f2tf(sc[nt][1]));
            *(uint2*)&sma[QP_W + (rm + gid + 8) * 68 + cc] =
                make_uint2(f2tf(sc[nt][2]), f2tf(sc[nt][3]));
        }
        __syncwarp();

        // ---- O += P . V  (both operands via ldmatrix) ----
#pragma unroll
        for (int ksp = 0; ksp < 8; ksp++) {
            const uint4 pf = ldsm4(sb + relP + (uint32_t)(ksp * 32));
#pragma unroll
            for (int n2 = 0; n2 < 4; n2++) {
                const uint4 vf = ldsm4(sb + vtoff + relV[n2] + (uint32_t)(ksp * 32));
                mma8(o[2 * n2],     pf.x, pf.y, pf.z, pf.w, vf.x, vf.y);
                mma8(o[2 * n2 + 1], pf.x, pf.y, pf.z, pf.w, vf.z, vf.w);
            }
        }

        __syncthreads();
        if (kt + 2 < 32) KV_ISSUE((kt + 2) * 64, kt & 1);
        cpcommit();
    }
#undef KV_ISSUE

    // ---- epilogue: normalize, tf32-round, write concat-head layout ----
    const float i1 = 1.f / l1;
    const float i2 = 1.f / l2;
    const int s1r = m0 + rm + gid;
    const int s2r = s1r + 8;
#pragma unroll
    for (int nt = 0; nt < 8; nt++) {
        const int n = nt * 8 + 2 * tig;
        *(float2*)&out[((size_t)bb * S + s1r) * D + hb * HD + n] =
            make_float2(rndtf(o[nt][0] * i1), rndtf(o[nt][1] * i1));
        *(float2*)&out[((size_t)bb * S + s2r) * D + hb * HD + n] =
            make_float2(rndtf(o[nt][2] * i2), rndtf(o[nt][3] * i2));
    }
}

// ---------------------------------------------------------------------------
// Launch
// ---------------------------------------------------------------------------
extern "C" void kernel_launch(void* const* d_in, const int* in_sizes, int n_in,
                              void* d_out, int out_size)
{
    const float* x  = (const float*)d_in[0];
    const float* Wq = (const float*)d_in[1];
    const float* bq = (const float*)d_in[2];
    const float* Wk = (const float*)d_in[3];
    const float* bk = (const float*)d_in[4];
    const float* Wv = (const float*)d_in[5];
    const float* bv = (const float*)d_in[6];
    const float* Wp = (const float*)d_in[7];
    const float* bp = (const float*)d_in[8];
    float* out = (float*)d_out;

    float *q, *k, *vt, *attn, *xt, *wt;
    cudaGetSymbolAddress((void**)&q,    g_q);
    cudaGetSymbolAddress((void**)&k,    g_k);
    cudaGetSymbolAddress((void**)&vt,   g_vt);
    cudaGetSymbolAddress((void**)&attn, g_attn);
    cudaGetSymbolAddress((void**)&xt,   g_xt);
    cudaGetSymbolAddress((void**)&wt,   g_wt);
    float* wqt = wt;
    float* wkt = wt + (size_t)D * D;
    float* wvt = wt + 2 * (size_t)D * D;
    float* wpt = wt + 3 * (size_t)D * D;

    const int smem_gemm = 4 * 16384;   // 65536
    const int smem_attn = 102400;

    cudaFuncSetAttribute(gemm_tc<2>, cudaFuncAttributeMaxDynamicSharedMemorySize, smem_gemm);
    cudaFuncSetAttribute(gemm_tc<0>, cudaFuncAttributeMaxDynamicSharedMemorySize, smem_gemm);
    cudaFuncSetAttribute(attn_tc,    cudaFuncAttributeMaxDynamicSharedMemorySize, smem_attn);

    tf32_cvt<<<dim3(512, 5), 256>>>(x, Wq, Wk, Wv, Wp, xt, wqt, wkt, wvt, wpt);

    gemm_tc<2><<<dim3(D / 128, M / 128, 3), 256, smem_gemm>>>(
        xt, wqt, bq, wkt, bk, wvt, bv, q, k, vt);

    attn_tc<<<dim3(S / 128, H, B), 256, smem_attn>>>(q, k, vt, attn);

    gemm_tc<0><<<dim3(D / 128, M / 128), 256, smem_gemm>>>(
        attn, wpt, bp, nullptr, nullptr, nullptr, nullptr, out, nullptr, nullptr);
}

// round 14
// speedup vs baseline: 1.0037x; 1.0037x over previous
#include <cuda_runtime.h>
#include <stdint.h>

constexpr int B  = 2;
constexpr int S  = 2048;
constexpr int D  = 1024;
constexpr int H  = 16;
constexpr int HD = 64;
constexpr int M  = B * S;   // 4096

// Scratch (device globals — no allocation allowed)
__device__ float g_q[(size_t)B * H * S * HD];
__device__ float g_k[(size_t)B * H * S * HD];
__device__ float g_v[(size_t)B * H * S * HD];
__device__ float g_attn[(size_t)B * S * D];
__device__ float g_xt[(size_t)M * D];          // tf32-rounded x
__device__ float g_wt[4 * (size_t)D * D];      // tf32-rounded Wq,Wk,Wv,Wp

__device__ __forceinline__ uint32_t f2tf(float f) {
    uint32_t u;
    asm("cvt.rna.tf32.f32 %0, %1;" : "=r"(u) : "f"(f));
    return u;
}
__device__ __forceinline__ float rndtf(float f) { return __uint_as_float(f2tf(f)); }

__device__ __forceinline__ void mma8(float* c,
                                     uint32_t a0, uint32_t a1, uint32_t a2, uint32_t a3,
                                     uint32_t b0, uint32_t b1) {
    asm volatile(
        "mma.sync.aligned.m16n8k8.row.col.f32.tf32.tf32.f32 "
        "{%0,%1,%2,%3},{%4,%5,%6,%7},{%8,%9},{%0,%1,%2,%3};"
        : "+f"(c[0]), "+f"(c[1]), "+f"(c[2]), "+f"(c[3])
        : "r"(a0), "r"(a1), "r"(a2), "r"(a3), "r"(b0), "r"(b1));
}

__device__ __forceinline__ uint4 ldsm4(uint32_t addr) {
    uint4 r;
    asm volatile("ldmatrix.sync.aligned.m8n8.x4.shared.b16 {%0,%1,%2,%3}, [%4];"
                 : "=r"(r.x), "=r"(r.y), "=r"(r.z), "=r"(r.w) : "r"(addr));
    return r;
}

__device__ __forceinline__ void cpa16(uint32_t dst, const void* src) {
    asm volatile("cp.async.cg.shared.global [%0], [%1], 16;" :: "r"(dst), "l"(src));
}
__device__ __forceinline__ void cpcommit() { asm volatile("cp.async.commit_group;"); }
template <int N>
__device__ __forceinline__ void cpwait() { asm volatile("cp.async.wait_group %0;" :: "n"(N)); }

// ---------------------------------------------------------------------------
// tf32 pre-round pass: x and the 4 weight matrices
// ---------------------------------------------------------------------------
__global__ __launch_bounds__(256)
void tf32_cvt(const float* __restrict__ x,  const float* __restrict__ wq,
              const float* __restrict__ wk, const float* __restrict__ wv,
              const float* __restrict__ wp,
              float* __restrict__ xo, float* __restrict__ qo,
              float* __restrict__ ko, float* __restrict__ vo, float* __restrict__ po)
{
    const float* s; float* d; int n;
    switch (blockIdx.y) {
        case 0: s = x;  d = xo; n = M * D; break;
        case 1: s = wq; d = qo; n = D * D; break;
        case 2: s = wk; d = ko; n = D * D; break;
        case 3: s = wv; d = vo; n = D * D; break;
        default: s = wp; d = po; n = D * D; break;
    }
    for (int i = (blockIdx.x * 256 + threadIdx.x) * 4; i < n; i += 512 * 256 * 4) {
        const float4 v = *(const float4*)(s + i);
        *(uint4*)(d + i) = make_uint4(f2tf(v.x), f2tf(v.y), f2tf(v.z), f2tf(v.w));
    }
}

// ---------------------------------------------------------------------------
// TF32 GEMM: C = A[M,1024] * W[1024,1024]^T + bias.  Inputs pre-rounded.
// Block 128x128, BK=16, 8 warps, warp tile 64x32. cp.async 4-stage pipeline
// (2 full stages in flight during compute). Smem stage s (16KB): A @ s*16384,
// B @ s*16384+8192; swizzle g^=((row>>1)&3).
// MODE 0: row-major fp32 out. MODE 2: QKV fused (z), tf32-rounded scatter
//         to [B,H,S,HD]; Q additionally scaled by 0.125.
// ---------------------------------------------------------------------------
template <int MODE>
__global__ __launch_bounds__(256, 2)
void gemm_tc(const float* __restrict__ A,
             const float* __restrict__ W0, const float* __restrict__ b0_,
             const float* __restrict__ W1, const float* __restrict__ b1_,
             const float* __restrict__ W2, const float* __restrict__ b2_,
             float* __restrict__ C0, float* __restrict__ C1, float* __restrict__ C2)
{
    constexpr int K = 1024;
    constexpr int N = 1024;
    constexpr int NKB = 64;

    const float* W; const float* bias; float* C; int z = 0;
    if (MODE != 2) { W = W0; bias = b0_; C = C0; }
    else {
        z    = blockIdx.z;
        W    = (z == 0) ? W0 : (z == 1) ? W1 : W2;
        bias = (z == 0) ? b0_ : (z == 1) ? b1_ : b2_;
        C    = (z == 0) ? C0 : (z == 1) ? C1 : C2;
    }

    extern __shared__ __align__(16) uint32_t smg[];
    const uint32_t sbase = (uint32_t)__cvta_generic_to_shared(smg);

    const int t    = threadIdx.x;
    const int lane = t & 31;
    const int warp = t >> 5;
    const int gid  = lane >> 2;
    const int tig  = lane & 3;
    const int wm   = warp >> 2;
    const int wn   = warp & 3;
    const int bm   = blockIdx.y * 128;
    const int bn   = blockIdx.x * 128;

    // cp.async staging
    const int srow = t >> 2;
    const int sg   = t & 3;
    const float* sa0 = A + (size_t)(bm + srow) * K + sg * 4;
    const float* sw0 = W + (size_t)(bn + srow) * K + sg * 4;
    const uint32_t dsw = (uint32_t)(srow * 64 + ((sg ^ ((srow >> 1) & 3)) << 4));

    // ldmatrix fragment addresses (byte offsets within a stage)
    uint32_t relA[4], relB[2];
    {
        const int hiA = (lane >> 4) & 1;
#pragma unroll
        for (int mt = 0; mt < 4; mt++) {
            const int row = wm * 64 + mt * 16 + (lane & 7) + (lane & 8);
            relA[mt] = row * 64 + (uint32_t)((hiA ^ ((row >> 1) & 3)) << 4);
        }
        const int hiB = (lane >> 3) & 1;
#pragma unroll
        for (int n2 = 0; n2 < 2; n2++) {
            const int row = wn * 32 + n2 * 16 + (lane & 7) + ((lane >> 1) & 8);
            relB[n2] = 8192u + row * 64 + (uint32_t)((hiB ^ ((row >> 1) & 3)) << 4);
        }
    }

#define GISSUE(kb, st)                                            \
    {                                                             \
        const uint32_t dd = sbase + (uint32_t)(st) * 16384u + dsw;\
        const float* a = sa0 + (kb) * 16;                         \
        const float* w = sw0 + (kb) * 16;                         \
        cpa16(dd,          a);                                    \
        cpa16(dd + 4096,   a + (size_t)64 * K);                   \
        cpa16(dd + 8192,   w);                                    \
        cpa16(dd + 12288,  w + (size_t)64 * K);                   \
    }

    float acc[4][4][4];
#pragma unroll
    for (int i = 0; i < 4; i++)
#pragma unroll
        for (int j = 0; j < 4; j++)
#pragma unroll
            for (int l = 0; l < 4; l++) acc[i][j][l] = 0.f;

    GISSUE(0, 0); cpcommit();
    GISSUE(1, 1); cpcommit();
    GISSUE(2, 2); cpcommit();

    for (int kb = 0; kb < NKB; kb++) {
        cpwait<2>();
        __syncthreads();
        if (kb + 3 < NKB) GISSUE(kb + 3, (kb + 3) & 3);
        cpcommit();

        const uint32_t sbk = sbase + (uint32_t)((kb & 3) << 14);
#pragma unroll
        for (int ks = 0; ks < 2; ks++) {
            const uint32_t kx = (uint32_t)(ks << 5);
            uint4 af[4];
#pragma unroll
            for (int mt = 0; mt < 4; mt++)
                af[mt] = ldsm4(sbk + (relA[mt] ^ kx));
            const uint4 bq0 = ldsm4(sbk + (relB[0] ^ kx));
            const uint4 bq1 = ldsm4(sbk + (relB[1] ^ kx));
#pragma unroll
            for (int mt = 0; mt < 4; mt++) {
                mma8(acc[mt][0], af[mt].x, af[mt].y, af[mt].z, af[mt].w, bq0.x, bq0.y);
                mma8(acc[mt][1], af[mt].x, af[mt].y, af[mt].z, af[mt].w, bq0.z, bq0.w);
                mma8(acc[mt][2], af[mt].x, af[mt].y, af[mt].z, af[mt].w, bq1.x, bq1.y);
                mma8(acc[mt][3], af[mt].x, af[mt].y, af[mt].z, af[mt].w, bq1.z, bq1.w);
            }
        }
    }
#undef GISSUE

    // ---- epilogue ----
    const float qs = (MODE == 2 && z == 0) ? 0.125f : 1.0f;
#pragma unroll
    for (int mt = 0; mt < 4; mt++) {
        const int r1 = bm + wm * 64 + mt * 16 + gid;
        const int r2 = r1 + 8;
#pragma unroll
        for (int nt = 0; nt < 4; nt++) {
            const int n = bn + wn * 32 + nt * 8 + 2 * tig;
            const float bx = __ldg(&bias[n]), by = __ldg(&bias[n + 1]);
            if (MODE == 0) {
                *(float2*)&C[(size_t)r1 * N + n] =
                    make_float2(acc[mt][nt][0] + bx, acc[mt][nt][1] + by);
                *(float2*)&C[(size_t)r2 * N + n] =
                    make_float2(acc[mt][nt][2] + bx, acc[mt][nt][3] + by);
            } else {
                float2 v1 = make_float2(rndtf((acc[mt][nt][0] + bx) * qs),
                                        rndtf((acc[mt][nt][1] + by) * qs));
                float2 v2 = make_float2(rndtf((acc[mt][nt][2] + bx) * qs),
                                        rndtf((acc[mt][nt][3] + by) * qs));
                const int hh = n >> 6, ee = n & 63;
                const int b1r = r1 >> 11, s1r = r1 & (S - 1);
                const int b2r = r2 >> 11, s2r = r2 & (S - 1);
                *(float2*)&C[(((size_t)b1r * H + hh) * S + s1r) * HD + ee] = v1;
                *(float2*)&C[(((size_t)b2r * H + hh) * S + s2r) * HD + ee] = v2;
            }
        }
    }
}

// ---------------------------------------------------------------------------
// TF32 flash attention (R8 configuration — the 435us-proven one).
// 64-row Q tiles, 128 threads (4 warps; warp owns 16 rows). cp.async
// double-buffered K/V; ldmatrix for Q, K (scores) and P (PV); V scalar LDS.
// Smem bytes: K0 @0, K1 @16384, V0 @32768, V1 @51200, Q @69632, P @86016.
// Total 103424 B. 2 CTAs/SM.
// ---------------------------------------------------------------------------
__global__ __launch_bounds__(128)
void attn_tc(const float* __restrict__ q,
             const float* __restrict__ k,
             const float* __restrict__ v,
             float* __restrict__ out)
{
    extern __shared__ __align__(16) uint32_t sma[];
    const uint32_t sb = (uint32_t)__cvta_generic_to_shared(sma);

    const int t    = threadIdx.x;
    const int lane = t & 31;
    const int warp = t >> 5;
    const int gid  = lane >> 2;
    const int tig  = lane & 3;
    const int rm   = warp * 16;

    const int hb = blockIdx.y, bb = blockIdx.z;
    const int m0 = blockIdx.x * 64;
    const size_t base = ((size_t)bb * H + hb) * S * HD;
    const float* qb  = q + base + (size_t)m0 * HD;
    const float* kb_ = k + base;
    const float* vb_ = v + base;

    const int crow = t >> 4;   // staging: chunk c = t + i*128 -> row crow+8i, group cg
    const int cg   = t & 15;

    // ---- issue Q (group 0) ----
#pragma unroll
    for (int i = 0; i < 8; i++) {
        const int row = crow + i * 8;
        cpa16(sb + 69632u + row * 256 + (uint32_t)((cg ^ (row & 7)) << 4),
              qb + row * 64 + cg * 4);
    }
    cpcommit();

#define KV_ISSUE(n0, buf)                                                        \
    {                                                                            \
        const float* kp = kb_ + (size_t)(n0) * HD;                               \
        const float* vp = vb_ + (size_t)(n0) * HD;                               \
        _Pragma("unroll")                                                        \
        for (int i = 0; i < 8; i++) {                                            \
            const int row = crow + i * 8;                                        \
            cpa16(sb + (uint32_t)(buf) * 16384u + row * 256 +                    \
                      (uint32_t)((cg ^ (row & 7)) << 4),                         \
                  kp + row * 64 + cg * 4);                                       \
        }                                                                        \
        _Pragma("unroll")                                                        \
        for (int i = 0; i < 8; i++) {                                            \
            const int row = crow + i * 8;                                        \
            cpa16(sb + 32768u + (uint32_t)(buf) * 18432u + row * 288 +           \
                      (uint32_t)(cg << 4),                                       \
                  vp + row * 64 + cg * 4);                                       \
        }                                                                        \
    }

    KV_ISSUE(0, 0);  cpcommit();
    KV_ISSUE(64, 1); cpcommit();

    // ---- fragment addresses ----
    uint32_t relK[4], relQ, relP;
    {
        const int hiB = (lane >> 3) & 1;
#pragma unroll
        for (int n2 = 0; n2 < 4; n2++) {
            const int row = n2 * 16 + (lane & 7) + ((lane >> 1) & 8);
            relK[n2] = row * 256 + (uint32_t)((hiB ^ (row & 7)) << 4);
        }
        const int hiA  = (lane >> 4) & 1;
        const int rowq = rm + (lane & 7) + (lane & 8);
        relQ = 69632u + rowq * 256 + (uint32_t)((hiA ^ (rowq & 7)) << 4);
        relP = 86016u + rowq * 272 + (uint32_t)(hiA << 4);
    }

    cpwait<2>();
    __syncthreads();
    uint4 qf[8];
#pragma unroll
    for (int ks = 0; ks < 8; ks++)
        qf[ks] = ldsm4(sb + (relQ ^ (uint32_t)(ks << 5)));

    float m1 = -1e30f, m2 = -1e30f, l1 = 0.f, l2 = 0.f;
    float o[8][4];
#pragma unroll
    for (int nt = 0; nt < 8; nt++)
#pragma unroll
        for (int j = 0; j < 4; j++) o[nt][j] = 0.f;

    for (int kt = 0; kt < 32; kt++) {
        cpwait<1>();
        __syncthreads();
        const uint32_t kbase = sb + (uint32_t)((kt & 1) << 14);
        const int vw = 8192 + (kt & 1) * 4608;

        // ---- scores = Q . K^T ----
        float sc[8][4];
#pragma unroll
        for (int nt = 0; nt < 8; nt++)
#pragma unroll
            for (int j = 0; j < 4; j++) sc[nt][j] = 0.f;
#pragma unroll
        for (int ks = 0; ks < 8; ks++) {
            const uint32_t kx = (uint32_t)(ks << 5);
#pragma unroll
            for (int n2 = 0; n2 < 4; n2++) {
                const uint4 bf = ldsm4(kbase + (relK[n2] ^ kx));
                mma8(sc[2 * n2],     qf[ks].x, qf[ks].y, qf[ks].z, qf[ks].w, bf.x, bf.y);
                mma8(sc[2 * n2 + 1], qf[ks].x, qf[ks].y, qf[ks].z, qf[ks].w, bf.z, bf.w);
            }
        }

        // ---- online softmax in registers ----
        float mx1 = -1e30f, mx2 = -1e30f;
#pragma unroll
        for (int nt = 0; nt < 8; nt++) {
            mx1 = fmaxf(mx1, fmaxf(sc[nt][0], sc[nt][1]));
            mx2 = fmaxf(mx2, fmaxf(sc[nt][2], sc[nt][3]));
        }
        mx1 = fmaxf(mx1, __shfl_xor_sync(0xffffffffu, mx1, 1));
        mx1 = fmaxf(mx1, __shfl_xor_sync(0xffffffffu, mx1, 2));
        mx2 = fmaxf(mx2, __shfl_xor_sync(0xffffffffu, mx2, 1));
        mx2 = fmaxf(mx2, __shfl_xor_sync(0xffffffffu, mx2, 2));
        const float M1 = fmaxf(m1, mx1);
        const float M2 = fmaxf(m2, mx2);

        float s1 = 0.f, s2 = 0.f;
#pragma unroll
        for (int nt = 0; nt < 8; nt++) {
            sc[nt][0] = __expf(sc[nt][0] - M1); s1 += sc[nt][0];
            sc[nt][1] = __expf(sc[nt][1] - M1); s1 += sc[nt][1];
            sc[nt][2] = __expf(sc[nt][2] - M2); s2 += sc[nt][2];
            sc[nt][3] = __expf(sc[nt][3] - M2); s2 += sc[nt][3];
        }
        s1 += __shfl_xor_sync(0xffffffffu, s1, 1);
        s1 += __shfl_xor_sync(0xffffffffu, s1, 2);
        s2 += __shfl_xor_sync(0xffffffffu, s2, 1);
        s2 += __shfl_xor_sync(0xffffffffu, s2, 2);

        const float c1 = __expf(m1 - M1);
        const float c2 = __expf(m2 - M2);
        l1 = l1 * c1 + s1;
        l2 = l2 * c2 + s2;
        m1 = M1; m2 = M2;
#pragma unroll
        for (int nt = 0; nt < 8; nt++) {
            o[nt][0] *= c1; o[nt][1] *= c1;
            o[nt][2] *= c2; o[nt][3] *= c2;
        }

        // ---- P -> smem (tf32), warp-private rows ----
#pragma unroll
        for (int nt = 0; nt < 8; nt++) {
            const int cc = nt * 8 + 2 * tig;
            *(uint2*)&sma[21504 + (rm + gid) * 68 + cc] =
                make_uint2(f2tf(sc[nt][0]), f2tf(sc[nt][1]));
            *(uint2*)&sma[21504 + (rm + gid + 8) * 68 + cc] =
                make_uint2(f2tf(sc[nt][2]), f2tf(sc[nt][3]));
        }
        __syncwarp();

        // ---- O += P . V ----
#pragma unroll
        for (int ksp = 0; ksp < 8; ksp++) {
            const uint4 pf = ldsm4(sb + relP + (uint32_t)(ksp * 32));
            const int vrow = vw + (ksp * 8 + tig) * 72;
#pragma unroll
            for (int nt = 0; nt < 8; nt++) {
                const uint32_t vb0 = sma[vrow + nt * 8 + gid];
                const uint32_t vb1 = sma[vrow + 288 + nt * 8 + gid];   // +4 rows
                mma8(o[nt], pf.x, pf.y, pf.z, pf.w, vb0, vb1);
            }
        }

        __syncthreads();
        if (kt + 2 < 32) KV_ISSUE((kt + 2) * 64, kt & 1);
        cpcommit();
    }
#undef KV_ISSUE

    // ---- epilogue: normalize, tf32-round, write concat-head layout ----
    const float i1 = 1.f / l1;
    const float i2 = 1.f / l2;
    const int s1r = m0 + rm + gid;
    const int s2r = s1r + 8;
#pragma unroll
    for (int nt = 0; nt < 8; nt++) {
        const int n = nt * 8 + 2 * tig;
        *(float2*)&out[((size_t)bb * S + s1r) * D + hb * HD + n] =
            make_float2(rndtf(o[nt][0] * i1), rndtf(o[nt][1] * i1));
        *(float2*)&out[((size_t)bb * S + s2r) * D + hb * HD + n] =
            make_float2(rndtf(o[nt][2] * i2), rndtf(o[nt][3] * i2));
    }
}

// ---------------------------------------------------------------------------
// Launch
// ---------------------------------------------------------------------------
extern "C" void kernel_launch(void* const* d_in, const int* in_sizes, int n_in,
                              void* d_out, int out_size)
{
    const float* x  = (const float*)d_in[0];
    const float* Wq = (const float*)d_in[1];
    const float* bq = (const float*)d_in[2];
    const float* Wk = (const float*)d_in[3];
    const float* bk = (const float*)d_in[4];
    const float* Wv = (const float*)d_in[5];
    const float* bv = (const float*)d_in[6];
    const float* Wp = (const float*)d_in[7];
    const float* bp = (const float*)d_in[8];
    float* out = (float*)d_out;

    float *q, *k, *v, *attn, *xt, *wt;
    cudaGetSymbolAddress((void**)&q,    g_q);
    cudaGetSymbolAddress((void**)&k,    g_k);
    cudaGetSymbolAddress((void**)&v,    g_v);
    cudaGetSymbolAddress((void**)&attn, g_attn);
    cudaGetSymbolAddress((void**)&xt,   g_xt);
    cudaGetSymbolAddress((void**)&wt,   g_wt);
    float* wqt = wt;
    float* wkt = wt + (size_t)D * D;
    float* wvt = wt + 2 * (size_t)D * D;
    float* wpt = wt + 3 * (size_t)D * D;

    const int smem_gemm = 4 * 16384;   // 65536
    const int smem_attn = 103424;

    cudaFuncSetAttribute(gemm_tc<2>, cudaFuncAttributeMaxDynamicSharedMemorySize, smem_gemm);
    cudaFuncSetAttribute(gemm_tc<0>, cudaFuncAttributeMaxDynamicSharedMemorySize, smem_gemm);
    cudaFuncSetAttribute(attn_tc,    cudaFuncAttributeMaxDynamicSharedMemorySize, smem_attn);

    tf32_cvt<<<dim3(512, 5), 256>>>(x, Wq, Wk, Wv, Wp, xt, wqt, wkt, wvt, wpt);

    gemm_tc<2><<<dim3(D / 128, M / 128, 3), 256, smem_gemm>>>(
        xt, wqt, bq, wkt, bk, wvt, bv, q, k, v);

    attn_tc<<<dim3(S / 64, H, B), 128, smem_attn>>>(q, k, v, attn);

    gemm_tc<0><<<dim3(D / 128, M / 128), 256, smem_gemm>>>(
        attn, wpt, bp, nullptr, nullptr, nullptr, nullptr, out, nullptr, nullptr);
}

// round 15
// speedup vs baseline: 1.7674x; 1.7608x over previous
#include <cuda_runtime.h>
#include <cuda_fp16.h>
#include <stdint.h>

constexpr int B  = 2;
constexpr int S  = 2048;
constexpr int D  = 1024;
constexpr int H  = 16;
constexpr int HD = 64;
constexpr int M  = B * S;   // 4096

// Scratch (device globals — no allocation allowed)
__device__ __half g_qh[(size_t)B * H * S * HD];
__device__ __half g_kh[(size_t)B * H * S * HD];
__device__ __half g_vh[(size_t)B * H * S * HD];
__device__ __half g_attnh[(size_t)B * S * D];
__device__ __half g_xh[(size_t)M * D];          // fp16 x
__device__ __half g_wh[4 * (size_t)D * D];      // fp16 Wq,Wk,Wv,Wp

__device__ __forceinline__ uint32_t pack_h2(float a, float b) {
    __half2 h = __floats2half2_rn(a, b);
    return *(uint32_t*)&h;
}

__device__ __forceinline__ void mma16(float* c,
                                      uint32_t a0, uint32_t a1, uint32_t a2, uint32_t a3,
                                      uint32_t b0, uint32_t b1) {
    asm volatile(
        "mma.sync.aligned.m16n8k16.row.col.f32.f16.f16.f32 "
        "{%0,%1,%2,%3},{%4,%5,%6,%7},{%8,%9},{%0,%1,%2,%3};"
        : "+f"(c[0]), "+f"(c[1]), "+f"(c[2]), "+f"(c[3])
        : "r"(a0), "r"(a1), "r"(a2), "r"(a3), "r"(b0), "r"(b1));
}

__device__ __forceinline__ uint4 ldsm4(uint32_t addr) {
    uint4 r;
    asm volatile("ldmatrix.sync.aligned.m8n8.x4.shared.b16 {%0,%1,%2,%3}, [%4];"
                 : "=r"(r.x), "=r"(r.y), "=r"(r.z), "=r"(r.w) : "r"(addr));
    return r;
}
__device__ __forceinline__ uint4 ldsm4t(uint32_t addr) {
    uint4 r;
    asm volatile("ldmatrix.sync.aligned.m8n8.x4.trans.shared.b16 {%0,%1,%2,%3}, [%4];"
                 : "=r"(r.x), "=r"(r.y), "=r"(r.z), "=r"(r.w) : "r"(addr));
    return r;
}

__device__ __forceinline__ void cpa16(uint32_t dst, const void* src) {
    asm volatile("cp.async.cg.shared.global [%0], [%1], 16;" :: "r"(dst), "l"(src));
}
__device__ __forceinline__ void cpcommit() { asm volatile("cp.async.commit_group;"); }
template <int N>
__device__ __forceinline__ void cpwait() { asm volatile("cp.async.wait_group %0;" :: "n"(N)); }

// ---------------------------------------------------------------------------
// fp16 convert pass: x and the 4 weight matrices (rounding happens HERE)
// ---------------------------------------------------------------------------
__global__ __launch_bounds__(256)
void h_cvt(const float* __restrict__ x,  const float* __restrict__ wq,
           const float* __restrict__ wk, const float* __restrict__ wv,
           const float* __restrict__ wp,
           __half* __restrict__ xo, __half* __restrict__ qo,
           __half* __restrict__ ko, __half* __restrict__ vo, __half* __restrict__ po)
{
    const float* s; __half* d; int n;
    switch (blockIdx.y) {
        case 0: s = x;  d = xo; n = M * D; break;
        case 1: s = wq; d = qo; n = D * D; break;
        case 2: s = wk; d = ko; n = D * D; break;
        case 3: s = wv; d = vo; n = D * D; break;
        default: s = wp; d = po; n = D * D; break;
    }
    for (int i = (blockIdx.x * 256 + threadIdx.x) * 4; i < n; i += 512 * 256 * 4) {
        const float4 v = *(const float4*)(s + i);
        uint2 o;
        o.x = pack_h2(v.x, v.y);
        o.y = pack_h2(v.z, v.w);
        *(uint2*)(d + i) = o;
    }
}

// ---------------------------------------------------------------------------
// FP16 GEMM: C = A[M,1024] * W[1024,1024]^T + bias (A,W fp16; accum fp32).
// Block 128x128, BK=32 halves (64B rows), 8 warps, warp tile 64x32.
// cp.async 4-stage pipeline; stage s (16KB): A @ s*16384, B @ +8192.
// Swizzle: 64B rows, chunk g ^= ((row>>1)&3). mma.m16n8k16.
// MODE 0: fp32 out [M,N]. MODE 2: QKV fused (z), fp16 scatter to [B,H,S,HD];
//         Q additionally scaled by 0.125.
// ---------------------------------------------------------------------------
template <int MODE>
__global__ __launch_bounds__(256, 2)
void gemm_h(const __half* __restrict__ A,
            const __half* __restrict__ W0, const float* __restrict__ b0_,
            const __half* __restrict__ W1, const float* __restrict__ b1_,
            const __half* __restrict__ W2, const float* __restrict__ b2_,
            float* __restrict__ Cf,
            __half* __restrict__ Ch0, __half* __restrict__ Ch1, __half* __restrict__ Ch2)
{
    constexpr int K = 1024;
    constexpr int N = 1024;
    constexpr int NKB = 32;   // BK = 32 halves

    const __half* W; const float* bias; __half* Ch = nullptr; int z = 0;
    if (MODE != 2) { W = W0; bias = b0_; }
    else {
        z    = blockIdx.z;
        W    = (z == 0) ? W0 : (z == 1) ? W1 : W2;
        bias = (z == 0) ? b0_ : (z == 1) ? b1_ : b2_;
        Ch   = (z == 0) ? Ch0 : (z == 1) ? Ch1 : Ch2;
    }

    extern __shared__ __align__(16) uint32_t smg[];
    const uint32_t sbase = (uint32_t)__cvta_generic_to_shared(smg);

    const int t    = threadIdx.x;
    const int lane = t & 31;
    const int warp = t >> 5;
    const int gid  = lane >> 2;
    const int tig  = lane & 3;
    const int wm   = warp >> 2;
    const int wn   = warp & 3;
    const int bm   = blockIdx.y * 128;
    const int bn   = blockIdx.x * 128;

    // cp.async staging: thread covers rows srow, srow+64; 16B chunk sg
    const int srow = t >> 2;
    const int sg   = t & 3;
    const __half* sa0 = A + (size_t)(bm + srow) * K + sg * 8;
    const __half* sw0 = W + (size_t)(bn + srow) * K + sg * 8;
    const uint32_t dsw = (uint32_t)(srow * 64 + ((sg ^ ((srow >> 1) & 3)) << 4));

    // ldmatrix fragment addresses (byte offsets within a stage)
    uint32_t relA[4], relB[2];
    {
        const int hi = lane >> 4;
#pragma unroll
        for (int mt = 0; mt < 4; mt++) {
            const int row = wm * 64 + mt * 16 + (lane & 7) + (lane & 8);
            relA[mt] = row * 64 + (uint32_t)((hi ^ ((row >> 1) & 3)) << 4);
        }
#pragma unroll
        for (int n2 = 0; n2 < 2; n2++) {
            const int row = wn * 32 + n2 * 16 + (lane & 7) + (lane & 8);
            relB[n2] = 8192u + row * 64 + (uint32_t)((hi ^ ((row >> 1) & 3)) << 4);
        }
    }

#define GISSUE(kb, st)                                            \
    {                                                             \
        const uint32_t dd = sbase + (uint32_t)(st) * 16384u + dsw;\
        const __half* a = sa0 + (kb) * 32;                        \
        const __half* w = sw0 + (kb) * 32;                        \
        cpa16(dd,          a);                                    \
        cpa16(dd + 4096,   a + (size_t)64 * K);                   \
        cpa16(dd + 8192,   w);                                    \
        cpa16(dd + 12288,  w + (size_t)64 * K);                   \
    }

    float acc[4][4][4];
#pragma unroll
    for (int i = 0; i < 4; i++)
#pragma unroll
        for (int j = 0; j < 4; j++)
#pragma unroll
            for (int l = 0; l < 4; l++) acc[i][j][l] = 0.f;

    GISSUE(0, 0); cpcommit();
    GISSUE(1, 1); cpcommit();
    GISSUE(2, 2); cpcommit();

    for (int kb = 0; kb < NKB; kb++) {
        cpwait<2>();
        __syncthreads();
        if (kb + 3 < NKB) GISSUE(kb + 3, (kb + 3) & 3);
        cpcommit();

        const uint32_t sbk = sbase + (uint32_t)((kb & 3) << 14);
#pragma unroll
        for (int ks = 0; ks < 2; ks++) {
            const uint32_t kx = (uint32_t)(ks << 5);
            uint4 af[4];
#pragma unroll
            for (int mt = 0; mt < 4; mt++)
                af[mt] = ldsm4(sbk + (relA[mt] ^ kx));
            const uint4 bq0 = ldsm4(sbk + (relB[0] ^ kx));
            const uint4 bq1 = ldsm4(sbk + (relB[1] ^ kx));
#pragma unroll
            for (int mt = 0; mt < 4; mt++) {
                mma16(acc[mt][0], af[mt].x, af[mt].y, af[mt].z, af[mt].w, bq0.x, bq0.z);
                mma16(acc[mt][1], af[mt].x, af[mt].y, af[mt].z, af[mt].w, bq0.y, bq0.w);
                mma16(acc[mt][2], af[mt].x, af[mt].y, af[mt].z, af[mt].w, bq1.x, bq1.z);
                mma16(acc[mt][3], af[mt].x, af[mt].y, af[mt].z, af[mt].w, bq1.y, bq1.w);
            }
        }
    }
#undef GISSUE

    // ---- epilogue ----
    const float qs = (MODE == 2 && z == 0) ? 0.125f : 1.0f;
#pragma unroll
    for (int mt = 0; mt < 4; mt++) {
        const int r1 = bm + wm * 64 + mt * 16 + gid;
        const int r2 = r1 + 8;
#pragma unroll
        for (int nt = 0; nt < 4; nt++) {
            const int n = bn + wn * 32 + nt * 8 + 2 * tig;
            const float bx = __ldg(&bias[n]), by = __ldg(&bias[n + 1]);
            if (MODE == 0) {
                *(float2*)&Cf[(size_t)r1 * N + n] =
                    make_float2(acc[mt][nt][0] + bx, acc[mt][nt][1] + by);
                *(float2*)&Cf[(size_t)r2 * N + n] =
                    make_float2(acc[mt][nt][2] + bx, acc[mt][nt][3] + by);
            } else {
                const uint32_t v1 = pack_h2((acc[mt][nt][0] + bx) * qs,
                                            (acc[mt][nt][1] + by) * qs);
                const uint32_t v2 = pack_h2((acc[mt][nt][2] + bx) * qs,
                                            (acc[mt][nt][3] + by) * qs);
                const int hh = n >> 6, ee = n & 63;
                const int b1r = r1 >> 11, s1r = r1 & (S - 1);
                const int b2r = r2 >> 11, s2r = r2 & (S - 1);
                *(uint32_t*)&Ch[(((size_t)b1r * H + hh) * S + s1r) * HD + ee] = v1;
                *(uint32_t*)&Ch[(((size_t)b2r * H + hh) * S + s2r) * HD + ee] = v2;
            }
        }
    }
}

// ---------------------------------------------------------------------------
// FP16 flash attention. 64-row Q tiles, 128 threads (4 warps; warp owns 16
// rows). cp.async double-buffered K/V. All operands via ldmatrix:
// Q/P A-frags, K B-frags, V B-frags via ldmatrix.trans (native transpose).
// Tiles: 64 rows x 128B (64 halves), swizzle chunk ^= (row&7).
// Smem bytes: K0 @0, K1 @8192, V0 @16384, V1 @24576, Q @32768, P @40960.
// Total 49152 B.
// ---------------------------------------------------------------------------
__global__ __launch_bounds__(128)
void attn_h(const __half* __restrict__ q,
            const __half* __restrict__ k,
            const __half* __restrict__ v,
            __half* __restrict__ out)
{
    extern __shared__ __align__(16) uint32_t sma[];
    const uint32_t sb = (uint32_t)__cvta_generic_to_shared(sma);

    const int t    = threadIdx.x;
    const int lane = t & 31;
    const int warp = t >> 5;
    const int gid  = lane >> 2;
    const int tig  = lane & 3;
    const int rm   = warp * 16;

    const int hb = blockIdx.y, bb = blockIdx.z;
    const int m0 = blockIdx.x * 64;
    const size_t base = ((size_t)bb * H + hb) * S * HD;
    const __half* qb  = q + base + (size_t)m0 * HD;
    const __half* kb_ = k + base;
    const __half* vb_ = v + base;

    // staging: chunk id = i*128 + t -> row = i*16 + (t>>3), cg = t&7
    const int cr = t >> 3;     // 0..15
    const int cg = t & 7;

    // ---- issue Q (group 0) ----
#pragma unroll
    for (int i = 0; i < 4; i++) {
        const int row = i * 16 + cr;
        cpa16(sb + 32768u + row * 128 + (uint32_t)((cg ^ (row & 7)) << 4),
              qb + row * 64 + cg * 8);
    }
    cpcommit();

#define KV_ISSUE(n0, buf)                                                        \
    {                                                                            \
        const __half* kp = kb_ + (size_t)(n0) * HD;                              \
        const __half* vp = vb_ + (size_t)(n0) * HD;                              \
        _Pragma("unroll")                                                        \
        for (int i = 0; i < 4; i++) {                                            \
            const int row = i * 16 + cr;                                         \
            const uint32_t sw = (uint32_t)((cg ^ (row & 7)) << 4);               \
            cpa16(sb + (uint32_t)(buf) * 8192u + row * 128 + sw,                 \
                  kp + row * 64 + cg * 8);                                       \
            cpa16(sb + 16384u + (uint32_t)(buf) * 8192u + row * 128 + sw,        \
                  vp + row * 64 + cg * 8);                                       \
        }                                                                        \
    }

    KV_ISSUE(0, 0);  cpcommit();
    KV_ISSUE(64, 1); cpcommit();

    // ---- fragment addresses ----
    uint32_t relK[4], relQ, relP, relV;
    {
        const int hi = lane >> 4;
#pragma unroll
        for (int n2 = 0; n2 < 4; n2++) {
            const int row = n2 * 16 + (lane & 7) + (lane & 8);
            relK[n2] = row * 128 + (uint32_t)((hi ^ (row & 7)) << 4);
        }
        const int rowq = rm + (lane & 7) + (lane & 8);
        relQ = 32768u + rowq * 128 + (uint32_t)((hi ^ (rowq & 7)) << 4);
        relP = 40960u + rowq * 128 + (uint32_t)((hi ^ (rowq & 7)) << 4);
        const int vrow = lane & 15;
        relV = 16384u + vrow * 128 + (uint32_t)((hi ^ (lane & 7)) << 4);
    }

    cpwait<2>();
    __syncthreads();
    uint4 qf[4];
#pragma unroll
    for (int ks = 0; ks < 4; ks++)
        qf[ks] = ldsm4(sb + (relQ ^ (uint32_t)(ks << 5)));

    float m1 = -1e30f, m2 = -1e30f, l1 = 0.f, l2 = 0.f;
    float o[8][4];
#pragma unroll
    for (int nt = 0; nt < 8; nt++)
#pragma unroll
        for (int j = 0; j < 4; j++) o[nt][j] = 0.f;

    for (int kt = 0; kt < 32; kt++) {
        cpwait<1>();
        __syncthreads();
        const uint32_t kbase = sb + (uint32_t)((kt & 1) << 13);
        const uint32_t voff  = (uint32_t)((kt & 1) << 13);

        // ---- scores = Q . K^T ----
        float sc[8][4];
#pragma unroll
        for (int nt = 0; nt < 8; nt++)
#pragma unroll
            for (int j = 0; j < 4; j++) sc[nt][j] = 0.f;
#pragma unroll
        for (int ks = 0; ks < 4; ks++) {
            const uint32_t kx = (uint32_t)(ks << 5);
#pragma unroll
            for (int n2 = 0; n2 < 4; n2++) {
                const uint4 bf = ldsm4(kbase + (relK[n2] ^ kx));
                mma16(sc[2 * n2],     qf[ks].x, qf[ks].y, qf[ks].z, qf[ks].w, bf.x, bf.z);
                mma16(sc[2 * n2 + 1], qf[ks].x, qf[ks].y, qf[ks].z, qf[ks].w, bf.y, bf.w);
            }
        }

        // ---- online softmax in registers ----
        float mx1 = -1e30f, mx2 = -1e30f;
#pragma unroll
        for (int nt = 0; nt < 8; nt++) {
            mx1 = fmaxf(mx1, fmaxf(sc[nt][0], sc[nt][1]));
            mx2 = fmaxf(mx2, fmaxf(sc[nt][2], sc[nt][3]));
        }
        mx1 = fmaxf(mx1, __shfl_xor_sync(0xffffffffu, mx1, 1));
        mx1 = fmaxf(mx1, __shfl_xor_sync(0xffffffffu, mx1, 2));
        mx2 = fmaxf(mx2, __shfl_xor_sync(0xffffffffu, mx2, 1));
        mx2 = fmaxf(mx2, __shfl_xor_sync(0xffffffffu, mx2, 2));
        const float M1 = fmaxf(m1, mx1);
        const float M2 = fmaxf(m2, mx2);

        float s1 = 0.f, s2 = 0.f;
#pragma unroll
        for (int nt = 0; nt < 8; nt++) {
            sc[nt][0] = __expf(sc[nt][0] - M1); s1 += sc[nt][0];
            sc[nt][1] = __expf(sc[nt][1] - M1); s1 += sc[nt][1];
            sc[nt][2] = __expf(sc[nt][2] - M2); s2 += sc[nt][2];
            sc[nt][3] = __expf(sc[nt][3] - M2); s2 += sc[nt][3];
        }
        s1 += __shfl_xor_sync(0xffffffffu, s1, 1);
        s1 += __shfl_xor_sync(0xffffffffu, s1, 2);
        s2 += __shfl_xor_sync(0xffffffffu, s2, 1);
        s2 += __shfl_xor_sync(0xffffffffu, s2, 2);

        const float c1 = __expf(m1 - M1);
        const float c2 = __expf(m2 - M2);
        l1 = l1 * c1 + s1;
        l2 = l2 * c2 + s2;
        m1 = M1; m2 = M2;
#pragma unroll
        for (int nt = 0; nt < 8; nt++) {
            o[nt][0] *= c1; o[nt][1] *= c1;
            o[nt][2] *= c2; o[nt][3] *= c2;
        }

        // ---- P -> smem (fp16), warp-private rows ----
        {
            const int row1 = rm + gid;
            const int row2 = row1 + 8;
#pragma unroll
            for (int nt = 0; nt < 8; nt++) {
                const uint32_t o1 = 40960u + row1 * 128 +
                                    (uint32_t)(((nt ^ (row1 & 7)) << 4) + tig * 4);
                const uint32_t o2 = 40960u + row2 * 128 +
                                    (uint32_t)(((nt ^ (row2 & 7)) << 4) + tig * 4);
                *(uint32_t*)((char*)sma + (o1 - 0)) = pack_h2(sc[nt][0], sc[nt][1]);
                *(uint32_t*)((char*)sma + (o2 - 0)) = pack_h2(sc[nt][2], sc[nt][3]);
            }
        }
        __syncwarp();

        // ---- O += P . V  (P via ldsm, V via ldsm.trans) ----
#pragma unroll
        for (int ksp = 0; ksp < 4; ksp++) {
            const uint4 pf = ldsm4(sb + (relP ^ (uint32_t)(ksp << 5)));
            const uint32_t vk = relV + voff + (uint32_t)(ksp * 2048);
#pragma unroll
            for (int n2 = 0; n2 < 4; n2++) {
                const uint4 vf = ldsm4t(sb + (vk ^ (uint32_t)(n2 << 5)));
                mma16(o[2 * n2],     pf.x, pf.y, pf.z, pf.w, vf.x, vf.y);
                mma16(o[2 * n2 + 1], pf.x, pf.y, pf.z, pf.w, vf.z, vf.w);
            }
        }

        __syncthreads();
        if (kt + 2 < 32) KV_ISSUE((kt + 2) * 64, kt & 1);
        cpcommit();
    }
#undef KV_ISSUE

    // ---- epilogue: normalize, fp16, write concat-head layout ----
    const float i1 = 1.f / l1;
    const float i2 = 1.f / l2;
    const int s1r = m0 + rm + gid;
    const int s2r = s1r + 8;
#pragma unroll
    for (int nt = 0; nt < 8; nt++) {
        const int n = nt * 8 + 2 * tig;
        *(uint32_t*)&out[((size_t)bb * S + s1r) * D + hb * HD + n] =
            pack_h2(o[nt][0] * i1, o[nt][1] * i1);
        *(uint32_t*)&out[((size_t)bb * S + s2r) * D + hb * HD + n] =
            pack_h2(o[nt][2] * i2, o[nt][3] * i2);
    }
}

// ---------------------------------------------------------------------------
// Launch
// ---------------------------------------------------------------------------
extern "C" void kernel_launch(void* const* d_in, const int* in_sizes, int n_in,
                              void* d_out, int out_size)
{
    const float* x  = (const float*)d_in[0];
    const float* Wq = (const float*)d_in[1];
    const float* bq = (const float*)d_in[2];
    const float* Wk = (const float*)d_in[3];
    const float* bk = (const float*)d_in[4];
    const float* Wv = (const float*)d_in[5];
    const float* bv = (const float*)d_in[6];
    const float* Wp = (const float*)d_in[7];
    const float* bp = (const float*)d_in[8];
    float* out = (float*)d_out;

    __half *qh, *kh, *vh, *attnh, *xh, *wh;
    cudaGetSymbolAddress((void**)&qh,    g_qh);
    cudaGetSymbolAddress((void**)&kh,    g_kh);
    cudaGetSymbolAddress((void**)&vh,    g_vh);
    cudaGetSymbolAddress((void**)&attnh, g_attnh);
    cudaGetSymbolAddress((void**)&xh,    g_xh);
    cudaGetSymbolAddress((void**)&wh,    g_wh);
    __half* wqh = wh;
    __half* wkh = wh + (size_t)D * D;
    __half* wvh = wh + 2 * (size_t)D * D;
    __half* wph = wh + 3 * (size_t)D * D;

    const int smem_gemm = 4 * 16384;   // 65536
    const int smem_attn = 49152;

    cudaFuncSetAttribute(gemm_h<2>, cudaFuncAttributeMaxDynamicSharedMemorySize, smem_gemm);
    cudaFuncSetAttribute(gemm_h<0>, cudaFuncAttributeMaxDynamicSharedMemorySize, smem_gemm);
    cudaFuncSetAttribute(attn_h,    cudaFuncAttributeMaxDynamicSharedMemorySize, smem_attn);

    h_cvt<<<dim3(512, 5), 256>>>(x, Wq, Wk, Wv, Wp, xh, wqh, wkh, wvh, wph);

    gemm_h<2><<<dim3(D / 128, M / 128, 3), 256, smem_gemm>>>(
        xh, wqh, bq, wkh, bk, wvh, bv, nullptr, qh, kh, vh);

    attn_h<<<dim3(S / 64, H, B), 128, smem_attn>>>(qh, kh, vh, attnh);

    gemm_h<0><<<dim3(D / 128, M / 128), 256, smem_gemm>>>(
        attnh, wph, bp, nullptr, nullptr, nullptr, nullptr, out, nullptr, nullptr, nullptr);
}

// round 16
// speedup vs baseline: 1.8636x; 1.0545x over previous
#include <cuda_runtime.h>
#include <cuda_fp16.h>
#include <stdint.h>

constexpr int B  = 2;
constexpr int S  = 2048;
constexpr int D  = 1024;
constexpr int H  = 16;
constexpr int HD = 64;
constexpr int M  = B * S;   // 4096

// Scratch (device globals — no allocation allowed)
__device__ __half g_qh[(size_t)B * H * S * HD];
__device__ __half g_kh[(size_t)B * H * S * HD];
__device__ __half g_vh[(size_t)B * H * S * HD];
__device__ __half g_attnh[(size_t)B * S * D];
__device__ __half g_xh[(size_t)M * D];          // fp16 x
__device__ __half g_wh[4 * (size_t)D * D];      // fp16 Wq,Wk,Wv,Wp

__device__ __forceinline__ uint32_t pack_h2(float a, float b) {
    __half2 h = __floats2half2_rn(a, b);
    return *(uint32_t*)&h;
}

__device__ __forceinline__ void mma16(float* c,
                                      uint32_t a0, uint32_t a1, uint32_t a2, uint32_t a3,
                                      uint32_t b0, uint32_t b1) {
    asm volatile(
        "mma.sync.aligned.m16n8k16.row.col.f32.f16.f16.f32 "
        "{%0,%1,%2,%3},{%4,%5,%6,%7},{%8,%9},{%0,%1,%2,%3};"
        : "+f"(c[0]), "+f"(c[1]), "+f"(c[2]), "+f"(c[3])
        : "r"(a0), "r"(a1), "r"(a2), "r"(a3), "r"(b0), "r"(b1));
}

__device__ __forceinline__ uint4 ldsm4(uint32_t addr) {
    uint4 r;
    asm volatile("ldmatrix.sync.aligned.m8n8.x4.shared.b16 {%0,%1,%2,%3}, [%4];"
                 : "=r"(r.x), "=r"(r.y), "=r"(r.z), "=r"(r.w) : "r"(addr));
    return r;
}
__device__ __forceinline__ uint4 ldsm4t(uint32_t addr) {
    uint4 r;
    asm volatile("ldmatrix.sync.aligned.m8n8.x4.trans.shared.b16 {%0,%1,%2,%3}, [%4];"
                 : "=r"(r.x), "=r"(r.y), "=r"(r.z), "=r"(r.w) : "r"(addr));
    return r;
}

// two exponentials (base-2) in one MUFU op on packed halves
__device__ __forceinline__ uint32_t ex2_h2(float a, float b) {
    __half2 h = __floats2half2_rn(a, b);
    uint32_t u = *(uint32_t*)&h;
    asm("ex2.approx.f16x2 %0, %0;" : "+r"(u));
    return u;
}

__device__ __forceinline__ void cpa16(uint32_t dst, const void* src) {
    asm volatile("cp.async.cg.shared.global [%0], [%1], 16;" :: "r"(dst), "l"(src));
}
__device__ __forceinline__ void cpcommit() { asm volatile("cp.async.commit_group;"); }
template <int N>
__device__ __forceinline__ void cpwait() { asm volatile("cp.async.wait_group %0;" :: "n"(N)); }

// ---------------------------------------------------------------------------
// fp16 convert pass: x and the 4 weight matrices (rounding happens HERE)
// ---------------------------------------------------------------------------
__global__ __launch_bounds__(256)
void h_cvt(const float* __restrict__ x,  const float* __restrict__ wq,
           const float* __restrict__ wk, const float* __restrict__ wv,
           const float* __restrict__ wp,
           __half* __restrict__ xo, __half* __restrict__ qo,
           __half* __restrict__ ko, __half* __restrict__ vo, __half* __restrict__ po)
{
    const float* s; __half* d; int n;
    switch (blockIdx.y) {
        case 0: s = x;  d = xo; n = M * D; break;
        case 1: s = wq; d = qo; n = D * D; break;
        case 2: s = wk; d = ko; n = D * D; break;
        case 3: s = wv; d = vo; n = D * D; break;
        default: s = wp; d = po; n = D * D; break;
    }
    for (int i = (blockIdx.x * 256 + threadIdx.x) * 4; i < n; i += 512 * 256 * 4) {
        const float4 v = *(const float4*)(s + i);
        uint2 o;
        o.x = pack_h2(v.x, v.y);
        o.y = pack_h2(v.z, v.w);
        *(uint2*)(d + i) = o;
    }
}

// ---------------------------------------------------------------------------
// FP16 GEMM (unchanged from R15): C = A * W^T + bias, fp32 accumulate.
// Block 128x128, BK=32 halves, 8 warps, warp tile 64x32, cp.async 4-stage.
// MODE 0: fp32 out. MODE 2: QKV fused (z), fp16 scatter; Q scaled 0.125.
// ---------------------------------------------------------------------------
template <int MODE>
__global__ __launch_bounds__(256, 2)
void gemm_h(const __half* __restrict__ A,
            const __half* __restrict__ W0, const float* __restrict__ b0_,
            const __half* __restrict__ W1, const float* __restrict__ b1_,
            const __half* __restrict__ W2, const float* __restrict__ b2_,
            float* __restrict__ Cf,
            __half* __restrict__ Ch0, __half* __restrict__ Ch1, __half* __restrict__ Ch2)
{
    constexpr int K = 1024;
    constexpr int N = 1024;
    constexpr int NKB = 32;   // BK = 32 halves

    const __half* W; const float* bias; __half* Ch = nullptr; int z = 0;
    if (MODE != 2) { W = W0; bias = b0_; }
    else {
        z    = blockIdx.z;
        W    = (z == 0) ? W0 : (z == 1) ? W1 : W2;
        bias = (z == 0) ? b0_ : (z == 1) ? b1_ : b2_;
        Ch   = (z == 0) ? Ch0 : (z == 1) ? Ch1 : Ch2;
    }

    extern __shared__ __align__(16) uint32_t smg[];
    const uint32_t sbase = (uint32_t)__cvta_generic_to_shared(smg);

    const int t    = threadIdx.x;
    const int lane = t & 31;
    const int warp = t >> 5;
    const int gid  = lane >> 2;
    const int tig  = lane & 3;
    const int wm   = warp >> 2;
    const int wn   = warp & 3;
    const int bm   = blockIdx.y * 128;
    const int bn   = blockIdx.x * 128;

    const int srow = t >> 2;
    const int sg   = t & 3;
    const __half* sa0 = A + (size_t)(bm + srow) * K + sg * 8;
    const __half* sw0 = W + (size_t)(bn + srow) * K + sg * 8;
    const uint32_t dsw = (uint32_t)(srow * 64 + ((sg ^ ((srow >> 1) & 3)) << 4));

    uint32_t relA[4], relB[2];
    {
        const int hi = lane >> 4;
#pragma unroll
        for (int mt = 0; mt < 4; mt++) {
            const int row = wm * 64 + mt * 16 + (lane & 7) + (lane & 8);
            relA[mt] = row * 64 + (uint32_t)((hi ^ ((row >> 1) & 3)) << 4);
        }
#pragma unroll
        for (int n2 = 0; n2 < 2; n2++) {
            const int row = wn * 32 + n2 * 16 + (lane & 7) + (lane & 8);
            relB[n2] = 8192u + row * 64 + (uint32_t)((hi ^ ((row >> 1) & 3)) << 4);
        }
    }

#define GISSUE(kb, st)                                            \
    {                                                             \
        const uint32_t dd = sbase + (uint32_t)(st) * 16384u + dsw;\
        const __half* a = sa0 + (kb) * 32;                        \
        const __half* w = sw0 + (kb) * 32;                        \
        cpa16(dd,          a);                                    \
        cpa16(dd + 4096,   a + (size_t)64 * K);                   \
        cpa16(dd + 8192,   w);                                    \
        cpa16(dd + 12288,  w + (size_t)64 * K);                   \
    }

    float acc[4][4][4];
#pragma unroll
    for (int i = 0; i < 4; i++)
#pragma unroll
        for (int j = 0; j < 4; j++)
#pragma unroll
            for (int l = 0; l < 4; l++) acc[i][j][l] = 0.f;

    GISSUE(0, 0); cpcommit();
    GISSUE(1, 1); cpcommit();
    GISSUE(2, 2); cpcommit();

    for (int kb = 0; kb < NKB; kb++) {
        cpwait<2>();
        __syncthreads();
        if (kb + 3 < NKB) GISSUE(kb + 3, (kb + 3) & 3);
        cpcommit();

        const uint32_t sbk = sbase + (uint32_t)((kb & 3) << 14);
#pragma unroll
        for (int ks = 0; ks < 2; ks++) {
            const uint32_t kx = (uint32_t)(ks << 5);
            uint4 af[4];
#pragma unroll
            for (int mt = 0; mt < 4; mt++)
                af[mt] = ldsm4(sbk + (relA[mt] ^ kx));
            const uint4 bq0 = ldsm4(sbk + (relB[0] ^ kx));
            const uint4 bq1 = ldsm4(sbk + (relB[1] ^ kx));
#pragma unroll
            for (int mt = 0; mt < 4; mt++) {
                mma16(acc[mt][0], af[mt].x, af[mt].y, af[mt].z, af[mt].w, bq0.x, bq0.z);
                mma16(acc[mt][1], af[mt].x, af[mt].y, af[mt].z, af[mt].w, bq0.y, bq0.w);
                mma16(acc[mt][2], af[mt].x, af[mt].y, af[mt].z, af[mt].w, bq1.x, bq1.z);
                mma16(acc[mt][3], af[mt].x, af[mt].y, af[mt].z, af[mt].w, bq1.y, bq1.w);
            }
        }
    }
#undef GISSUE

    // ---- epilogue ----
    const float qs = (MODE == 2 && z == 0) ? 0.125f : 1.0f;
#pragma unroll
    for (int mt = 0; mt < 4; mt++) {
        const int r1 = bm + wm * 64 + mt * 16 + gid;
        const int r2 = r1 + 8;
#pragma unroll
        for (int nt = 0; nt < 4; nt++) {
            const int n = bn + wn * 32 + nt * 8 + 2 * tig;
            const float bx = __ldg(&bias[n]), by = __ldg(&bias[n + 1]);
            if (MODE == 0) {
                *(float2*)&Cf[(size_t)r1 * N + n] =
                    make_float2(acc[mt][nt][0] + bx, acc[mt][nt][1] + by);
                *(float2*)&Cf[(size_t)r2 * N + n] =
                    make_float2(acc[mt][nt][2] + bx, acc[mt][nt][3] + by);
            } else {
                const uint32_t v1 = pack_h2((acc[mt][nt][0] + bx) * qs,
                                            (acc[mt][nt][1] + by) * qs);
                const uint32_t v2 = pack_h2((acc[mt][nt][2] + bx) * qs,
                                            (acc[mt][nt][3] + by) * qs);
                const int hh = n >> 6, ee = n & 63;
                const int b1r = r1 >> 11, s1r = r1 & (S - 1);
                const int b2r = r2 >> 11, s2r = r2 & (S - 1);
                *(uint32_t*)&Ch[(((size_t)b1r * H + hh) * S + s1r) * HD + ee] = v1;
                *(uint32_t*)&Ch[(((size_t)b2r * H + hh) * S + s2r) * HD + ee] = v2;
            }
        }
    }
}

// ---------------------------------------------------------------------------
// FP16 flash attention (R15 structure). Softmax now uses ex2.approx.f16x2:
// 2 exponentials per MUFU op; results are the exact f16 P values stored for
// the PV MMA, and l sums those same f16 values.
// Smem bytes: K0 @0, K1 @8192, V0 @16384, V1 @24576, Q @32768, P @40960.
// Total 49152 B.
// ---------------------------------------------------------------------------
__global__ __launch_bounds__(128)
void attn_h(const __half* __restrict__ q,
            const __half* __restrict__ k,
            const __half* __restrict__ v,
            __half* __restrict__ out)
{
    extern __shared__ __align__(16) uint32_t sma[];
    const uint32_t sb = (uint32_t)__cvta_generic_to_shared(sma);

    const int t    = threadIdx.x;
    const int lane = t & 31;
    const int warp = t >> 5;
    const int gid  = lane >> 2;
    const int tig  = lane & 3;
    const int rm   = warp * 16;

    const int hb = blockIdx.y, bb = blockIdx.z;
    const int m0 = blockIdx.x * 64;
    const size_t base = ((size_t)bb * H + hb) * S * HD;
    const __half* qb  = q + base + (size_t)m0 * HD;
    const __half* kb_ = k + base;
    const __half* vb_ = v + base;

    const int cr = t >> 3;     // 0..15
    const int cg = t & 7;

    // ---- issue Q (group 0) ----
#pragma unroll
    for (int i = 0; i < 4; i++) {
        const int row = i * 16 + cr;
        cpa16(sb + 32768u + row * 128 + (uint32_t)((cg ^ (row & 7)) << 4),
              qb + row * 64 + cg * 8);
    }
    cpcommit();

#define KV_ISSUE(n0, buf)                                                        \
    {                                                                            \
        const __half* kp = kb_ + (size_t)(n0) * HD;                              \
        const __half* vp = vb_ + (size_t)(n0) * HD;                              \
        _Pragma("unroll")                                                        \
        for (int i = 0; i < 4; i++) {                                            \
            const int row = i * 16 + cr;                                         \
            const uint32_t sw = (uint32_t)((cg ^ (row & 7)) << 4);               \
            cpa16(sb + (uint32_t)(buf) * 8192u + row * 128 + sw,                 \
                  kp + row * 64 + cg * 8);                                       \
            cpa16(sb + 16384u + (uint32_t)(buf) * 8192u + row * 128 + sw,        \
                  vp + row * 64 + cg * 8);                                       \
        }                                                                        \
    }

    KV_ISSUE(0, 0);  cpcommit();
    KV_ISSUE(64, 1); cpcommit();

    // ---- fragment addresses ----
    uint32_t relK[4], relQ, relP, relV;
    {
        const int hi = lane >> 4;
#pragma unroll
        for (int n2 = 0; n2 < 4; n2++) {
            const int row = n2 * 16 + (lane & 7) + (lane & 8);
            relK[n2] = row * 128 + (uint32_t)((hi ^ (row & 7)) << 4);
        }
        const int rowq = rm + (lane & 7) + (lane & 8);
        relQ = 32768u + rowq * 128 + (uint32_t)((hi ^ (rowq & 7)) << 4);
        relP = 40960u + rowq * 128 + (uint32_t)((hi ^ (rowq & 7)) << 4);
        const int vrow = lane & 15;
        relV = 16384u + vrow * 128 + (uint32_t)((hi ^ (lane & 7)) << 4);
    }

    cpwait<2>();
    __syncthreads();
    uint4 qf[4];
#pragma unroll
    for (int ks = 0; ks < 4; ks++)
        qf[ks] = ldsm4(sb + (relQ ^ (uint32_t)(ks << 5)));

    constexpr float L2E = 1.4426950408889634f;
    float m1 = -1e30f, m2 = -1e30f, l1 = 0.f, l2 = 0.f;
    float o[8][4];
#pragma unroll
    for (int nt = 0; nt < 8; nt++)
#pragma unroll
        for (int j = 0; j < 4; j++) o[nt][j] = 0.f;

    for (int kt = 0; kt < 32; kt++) {
        cpwait<1>();
        __syncthreads();
        const uint32_t kbase = sb + (uint32_t)((kt & 1) << 13);
        const uint32_t voff  = (uint32_t)((kt & 1) << 13);

        // ---- scores = Q . K^T ----
        float sc[8][4];
#pragma unroll
        for (int nt = 0; nt < 8; nt++)
#pragma unroll
            for (int j = 0; j < 4; j++) sc[nt][j] = 0.f;
#pragma unroll
        for (int ks = 0; ks < 4; ks++) {
            const uint32_t kx = (uint32_t)(ks << 5);
#pragma unroll
            for (int n2 = 0; n2 < 4; n2++) {
                const uint4 bf = ldsm4(kbase + (relK[n2] ^ kx));
                mma16(sc[2 * n2],     qf[ks].x, qf[ks].y, qf[ks].z, qf[ks].w, bf.x, bf.z);
                mma16(sc[2 * n2 + 1], qf[ks].x, qf[ks].y, qf[ks].z, qf[ks].w, bf.y, bf.w);
            }
        }

        // ---- online softmax: max in fp32, exp via ex2.approx.f16x2 ----
        float mx1 = -1e30f, mx2 = -1e30f;
#pragma unroll
        for (int nt = 0; nt < 8; nt++) {
            mx1 = fmaxf(mx1, fmaxf(sc[nt][0], sc[nt][1]));
            mx2 = fmaxf(mx2, fmaxf(sc[nt][2], sc[nt][3]));
        }
        mx1 = fmaxf(mx1, __shfl_xor_sync(0xffffffffu, mx1, 1));
        mx1 = fmaxf(mx1, __shfl_xor_sync(0xffffffffu, mx1, 2));
        mx2 = fmaxf(mx2, __shfl_xor_sync(0xffffffffu, mx2, 1));
        mx2 = fmaxf(mx2, __shfl_xor_sync(0xffffffffu, mx2, 2));
        const float M1 = fmaxf(m1, mx1);
        const float M2 = fmaxf(m2, mx2);

        uint32_t ph1[8], ph2[8];   // f16x2 P values (rows r, r+8)
        float s1 = 0.f, s2 = 0.f;
#pragma unroll
        for (int nt = 0; nt < 8; nt++) {
            ph1[nt] = ex2_h2((sc[nt][0] - M1) * L2E, (sc[nt][1] - M1) * L2E);
            ph2[nt] = ex2_h2((sc[nt][2] - M2) * L2E, (sc[nt][3] - M2) * L2E);
            const float2 f1 = __half22float2(*(__half2*)&ph1[nt]);
            const float2 f2 = __half22float2(*(__half2*)&ph2[nt]);
            s1 += f1.x + f1.y;
            s2 += f2.x + f2.y;
        }
        s1 += __shfl_xor_sync(0xffffffffu, s1, 1);
        s1 += __shfl_xor_sync(0xffffffffu, s1, 2);
        s2 += __shfl_xor_sync(0xffffffffu, s2, 1);
        s2 += __shfl_xor_sync(0xffffffffu, s2, 2);

        const float c1 = __expf(m1 - M1);
        const float c2 = __expf(m2 - M2);
        l1 = l1 * c1 + s1;
        l2 = l2 * c2 + s2;
        m1 = M1; m2 = M2;
#pragma unroll
        for (int nt = 0; nt < 8; nt++) {
            o[nt][0] *= c1; o[nt][1] *= c1;
            o[nt][2] *= c2; o[nt][3] *= c2;
        }

        // ---- P -> smem (already f16x2), warp-private rows ----
        {
            const int row1 = rm + gid;
            const int row2 = row1 + 8;
#pragma unroll
            for (int nt = 0; nt < 8; nt++) {
                const uint32_t o1 = 40960u + row1 * 128 +
                                    (uint32_t)(((nt ^ (row1 & 7)) << 4) + tig * 4);
                const uint32_t o2 = 40960u + row2 * 128 +
                                    (uint32_t)(((nt ^ (row2 & 7)) << 4) + tig * 4);
                *(uint32_t*)((char*)sma + o1) = ph1[nt];
                *(uint32_t*)((char*)sma + o2) = ph2[nt];
            }
        }
        __syncwarp();

        // ---- O += P . V  (P via ldsm, V via ldsm.trans) ----
#pragma unroll
        for (int ksp = 0; ksp < 4; ksp++) {
            const uint4 pf = ldsm4(sb + (relP ^ (uint32_t)(ksp << 5)));
            const uint32_t vk = relV + voff + (uint32_t)(ksp * 2048);
#pragma unroll
            for (int n2 = 0; n2 < 4; n2++) {
                const uint4 vf = ldsm4t(sb + (vk ^ (uint32_t)(n2 << 5)));
                mma16(o[2 * n2],     pf.x, pf.y, pf.z, pf.w, vf.x, vf.y);
                mma16(o[2 * n2 + 1], pf.x, pf.y, pf.z, pf.w, vf.z, vf.w);
            }
        }

        __syncthreads();
        if (kt + 2 < 32) KV_ISSUE((kt + 2) * 64, kt & 1);
        cpcommit();
    }
#undef KV_ISSUE

    // ---- epilogue: normalize, fp16, write concat-head layout ----
    const float i1 = 1.f / l1;
    const float i2 = 1.f / l2;
    const int s1r = m0 + rm + gid;
    const int s2r = s1r + 8;
#pragma unroll
    for (int nt = 0; nt < 8; nt++) {
        const int n = nt * 8 + 2 * tig;
        *(uint32_t*)&out[((size_t)bb * S + s1r) * D + hb * HD + n] =
            pack_h2(o[nt][0] * i1, o[nt][1] * i1);
        *(uint32_t*)&out[((size_t)bb * S + s2r) * D + hb * HD + n] =
            pack_h2(o[nt][2] * i2, o[nt][3] * i2);
    }
}

// ---------------------------------------------------------------------------
// Launch
// ---------------------------------------------------------------------------
extern "C" void kernel_launch(void* const* d_in, const int* in_sizes, int n_in,
                              void* d_out, int out_size)
{
    const float* x  = (const float*)d_in[0];
    const float* Wq = (const float*)d_in[1];
    const float* bq = (const float*)d_in[2];
    const float* Wk = (const float*)d_in[3];
    const float* bk = (const float*)d_in[4];
    const float* Wv = (const float*)d_in[5];
    const float* bv = (const float*)d_in[6];
    const float* Wp = (const float*)d_in[7];
    const float* bp = (const float*)d_in[8];
    float* out = (float*)d_out;

    __half *qh, *kh, *vh, *attnh, *xh, *wh;
    cudaGetSymbolAddress((void**)&qh,    g_qh);
    cudaGetSymbolAddress((void**)&kh,    g_kh);
    cudaGetSymbolAddress((void**)&vh,    g_vh);
    cudaGetSymbolAddress((void**)&attnh, g_attnh);
    cudaGetSymbolAddress((void**)&xh,    g_xh);
    cudaGetSymbolAddress((void**)&wh,    g_wh);
    __half* wqh = wh;
    __half* wkh = wh + (size_t)D * D;
    __half* wvh = wh + 2 * (size_t)D * D;
    __half* wph = wh + 3 * (size_t)D * D;

    const int smem_gemm = 4 * 16384;   // 65536
    const int smem_attn = 49152;

    cudaFuncSetAttribute(gemm_h<2>, cudaFuncAttributeMaxDynamicSharedMemorySize, smem_gemm);
    cudaFuncSetAttribute(gemm_h<0>, cudaFuncAttributeMaxDynamicSharedMemorySize, smem_gemm);
    cudaFuncSetAttribute(attn_h,    cudaFuncAttributeMaxDynamicSharedMemorySize, smem_attn);

    h_cvt<<<dim3(512, 5), 256>>>(x, Wq, Wk, Wv, Wp, xh, wqh, wkh, wvh, wph);

    gemm_h<2><<<dim3(D / 128, M / 128, 3), 256, smem_gemm>>>(
        xh, wqh, bq, wkh, bk, wvh, bv, nullptr, qh, kh, vh);

    attn_h<<<dim3(S / 64, H, B), 128, smem_attn>>>(qh, kh, vh, attnh);

    gemm_h<0><<<dim3(D / 128, M / 128), 256, smem_gemm>>>(
        attnh, wph, bp, nullptr, nullptr, nullptr, nullptr, out, nullptr, nullptr, nullptr);
}